// round 1
// baseline (speedup 1.0000x reference)
#include <cuda_runtime.h>
#include <cuda_bf16.h>
#include <math.h>

#define TT 2048
#define DIM 1024
#define NH 16
#define HD 64
#define WIN 16
#define KS 33           // 2*WIN+1
#define NG 32           // global tokens (t % 64 == 0)
#define NKEY (KS + NG)  // 65

// Scratch (device globals, no allocation)
__device__ float g_Q[TT * DIM];
__device__ float g_K[TT * DIM];
__device__ float g_V[TT * DIM];
__device__ float g_CTX[TT * DIM];

// ---------------------------------------------------------------------------
// SGEMM (NT): C[M,N] = A[M,K] * B[N,K]^T  (both row-major; dot of rows)
// 64x64 tile, 16 k-slab, 256 threads, 4x4 per thread.
// ---------------------------------------------------------------------------
__global__ __launch_bounds__(256) void sgemm_nt(const float* __restrict__ A,
                                                const float* __restrict__ B,
                                                float* __restrict__ C,
                                                int M, int N, int K) {
    __shared__ float As[16][68];  // [k][i], padded to 68 (bank-friendly, 16B-multiple)
    __shared__ float Bs[16][68];  // [k][j]

    const int tx = threadIdx.x & 15;
    const int ty = threadIdx.x >> 4;
    const int row0 = blockIdx.y * 64;
    const int col0 = blockIdx.x * 64;

    const int lk = threadIdx.x & 15;   // 0..15
    const int li = threadIdx.x >> 4;   // 0..15

    float acc[4][4];
#pragma unroll
    for (int i = 0; i < 4; i++)
#pragma unroll
        for (int j = 0; j < 4; j++) acc[i][j] = 0.f;

    for (int k0 = 0; k0 < K; k0 += 16) {
#pragma unroll
        for (int r = 0; r < 4; r++) {
            int i = li + 16 * r;
            As[lk][i] = A[(size_t)(row0 + i) * K + k0 + lk];
            Bs[lk][i] = B[(size_t)(col0 + i) * K + k0 + lk];
        }
        __syncthreads();
#pragma unroll
        for (int k = 0; k < 16; k++) {
            float a[4], b[4];
#pragma unroll
            for (int u = 0; u < 4; u++) a[u] = As[k][ty * 4 + u];
#pragma unroll
            for (int u = 0; u < 4; u++) b[u] = Bs[k][tx * 4 + u];
#pragma unroll
            for (int i = 0; i < 4; i++)
#pragma unroll
                for (int j = 0; j < 4; j++) acc[i][j] += a[i] * b[j];
        }
        __syncthreads();
    }

#pragma unroll
    for (int i = 0; i < 4; i++) {
        float* cp = C + (size_t)(row0 + ty * 4 + i) * N + col0 + tx * 4;
#pragma unroll
        for (int j = 0; j < 4; j++) cp[j] = acc[i][j];
    }
}

// ---------------------------------------------------------------------------
// RoPE over Q and K, interleaved pairs. One thread per (t, h, pair i).
// ---------------------------------------------------------------------------
__global__ void rope_kernel(float* __restrict__ Q, float* __restrict__ K) {
    int idx = blockIdx.x * blockDim.x + threadIdx.x;
    const int total = TT * NH * (HD / 2);
    if (idx >= total) return;
    int i = idx & 31;            // pair index 0..31
    int rem = idx >> 5;
    int h = rem & (NH - 1);
    int t = rem >> 4;

    float invf = powf(10000.0f, -((float)i) / 32.0f);
    float ang = (float)t * invf;
    float s, c;
    sincosf(ang, &s, &c);

    int base = t * DIM + h * HD + 2 * i;
    float q1 = Q[base], q2 = Q[base + 1];
    Q[base]     = q1 * c - q2 * s;
    Q[base + 1] = q1 * s + q2 * c;
    float k1 = K[base], k2 = K[base + 1];
    K[base]     = k1 * c - k2 * s;
    K[base + 1] = k1 * s + k2 * c;
}

// ---------------------------------------------------------------------------
// Attention: one block per (t, h). 128 threads.
//   scores (65 keys: 33 local incl. zero-pad slots with logit 0, 32 global)
//   -> softmax -> ctx -> scatter weights into `full`.
// ---------------------------------------------------------------------------
__global__ __launch_bounds__(128) void attn_kernel(const float* __restrict__ Q,
                                                   const float* __restrict__ K,
                                                   const float* __restrict__ V,
                                                   float* __restrict__ CTX,
                                                   float* __restrict__ full) {
    const int t = blockIdx.x;
    const int h = blockIdx.y;
    const int tid = threadIdx.x;

    __shared__ float sq[HD];
    __shared__ float w[NKEY];
    __shared__ float sinv;

    if (tid < HD) sq[tid] = Q[(size_t)t * DIM + h * HD + tid];
    __syncthreads();

    if (tid < NKEY) {
        float s = 0.f;
        int pos;
        bool valid = true;
        if (tid < KS) {
            pos = t - WIN + tid;
            valid = (pos >= 0 && pos < TT);
        } else {
            pos = (tid - KS) * 64;
        }
        if (valid) {
            const float* kr = K + (size_t)pos * DIM + h * HD;
#pragma unroll
            for (int d = 0; d < HD; d++) s += sq[d] * kr[d];
            s *= 0.125f;  // 1/sqrt(64)
        }
        w[tid] = s;  // invalid local slot: logit = 0 exactly (zero-padded K)
    }
    __syncthreads();

    if (tid == 0) {
        float m = -1e30f;
#pragma unroll 1
        for (int i = 0; i < NKEY; i++) m = fmaxf(m, w[i]);
        float sum = 0.f;
#pragma unroll 1
        for (int i = 0; i < NKEY; i++) {
            float e = expf(w[i] - m);
            w[i] = e;
            sum += e;
        }
        sinv = 1.f / sum;
    }
    __syncthreads();
    if (tid < NKEY) w[tid] *= sinv;
    __syncthreads();

    // Context: thread d accumulates over keys (coalesced V reads along d).
    if (tid < HD) {
        float acc = 0.f;
#pragma unroll 1
        for (int i = 0; i < KS; i++) {
            int pos = t - WIN + i;
            if (pos >= 0 && pos < TT)
                acc += w[i] * V[(size_t)pos * DIM + h * HD + tid];
        }
#pragma unroll 1
        for (int g = 0; g < NG; g++)
            acc += w[KS + g] * V[(size_t)(g * 64) * DIM + h * HD + tid];
        CTX[(size_t)t * DIM + h * HD + tid] = acc;
    }

    // Scatter into full[h][t][col] (exact reference semantics)
    if (tid < NKEY) {
        float* rowp = full + ((size_t)h * TT + t) * TT;
        if (tid < KS) {
            int left = max(t - WIN, 0);
            int col = left + tid;
            int right = min(t + WIN + 1, TT);
            if (col < right) atomicAdd(rowp + col, w[tid]);
        } else {
            atomicAdd(rowp + (tid - KS) * 64, w[tid]);
        }
    }
}

// ---------------------------------------------------------------------------
// kernel_launch
// inputs: x[2048*1024], Wq, Wk, Wv, Wo [1024*1024], global_mask (ignored:
//         deterministic t%64==0)
// output: out (2048*1024 f32) followed by full (16*2048*2048 f32)
// ---------------------------------------------------------------------------
extern "C" void kernel_launch(void* const* d_in, const int* in_sizes, int n_in,
                              void* d_out, int out_size) {
    const float* x  = (const float*)d_in[0];
    const float* Wq = (const float*)d_in[1];
    const float* Wk = (const float*)d_in[2];
    const float* Wv = (const float*)d_in[3];
    const float* Wo = (const float*)d_in[4];

    float* out  = (float*)d_out;
    float* full = (float*)d_out + (size_t)TT * DIM;

    float *Q, *Kb, *V, *CTX;
    cudaGetSymbolAddress((void**)&Q,   g_Q);
    cudaGetSymbolAddress((void**)&Kb,  g_K);
    cudaGetSymbolAddress((void**)&V,   g_V);
    cudaGetSymbolAddress((void**)&CTX, g_CTX);

    // Zero the `full` region (out region is fully overwritten by final GEMM).
    cudaMemsetAsync(full, 0, (size_t)NH * TT * TT * sizeof(float));

    dim3 gg(DIM / 64, TT / 64);  // (16, 32)
    sgemm_nt<<<gg, 256>>>(x, Wq, Q,  TT, DIM, DIM);
    sgemm_nt<<<gg, 256>>>(x, Wk, Kb, TT, DIM, DIM);
    sgemm_nt<<<gg, 256>>>(x, Wv, V,  TT, DIM, DIM);

    {
        int total = TT * NH * (HD / 2);
        rope_kernel<<<(total + 255) / 256, 256>>>(Q, Kb);
    }

    dim3 ga(TT, NH);
    attn_kernel<<<ga, 128>>>(Q, Kb, V, CTX, full);

    sgemm_nt<<<gg, 256>>>(CTX, Wo, out, TT, DIM, DIM);
}

// round 4
// speedup vs baseline: 3.2390x; 3.2390x over previous
#include <cuda_runtime.h>
#include <cuda_bf16.h>
#include <math.h>
#include <cstdint>

#define TT 2048
#define DIM 1024
#define NH 16
#define HD 64
#define WIN 16
#define KS 33
#define NG 32
#define NKEY (KS + NG)

// ---------------- scratch (device globals, no allocation) ----------------
__device__ float g_Q[TT * DIM];
__device__ float g_K[TT * DIM];
__device__ float g_V[TT * DIM];
__device__ float g_CTX[TT * DIM];
__device__ __nv_bfloat16 g_xh[TT * DIM], g_xl[TT * DIM];
__device__ __nv_bfloat16 g_wh[4][DIM * DIM], g_wl[4][DIM * DIM];
__device__ __nv_bfloat16 g_ch[TT * DIM], g_cl[TT * DIM];

// ---------------- PTX helpers (sm_80-generic only!) ----------------
__device__ __forceinline__ uint32_t s2u(const void* p) {
    uint32_t a;
    asm("{ .reg .u64 t; cvta.to.shared.u64 t, %1; cvt.u32.u64 %0, t; }" : "=r"(a) : "l"(p));
    return a;
}
__device__ __forceinline__ void cp16(uint32_t saddr, const void* g) {
    asm volatile("cp.async.cg.shared.global [%0], [%1], 16;" :: "r"(saddr), "l"(g));
}
__device__ __forceinline__ void cp_commit() {
    asm volatile("cp.async.commit_group;" ::: "memory");
}
template <int N>
__device__ __forceinline__ void cp_wait() {
    asm volatile("cp.async.wait_group %0;" :: "n"(N) : "memory");
}
__device__ __forceinline__ void ldsm4(uint32_t* r, uint32_t a) {
    asm volatile("ldmatrix.sync.aligned.m8n8.x4.shared.b16 {%0,%1,%2,%3}, [%4];"
                 : "=r"(r[0]), "=r"(r[1]), "=r"(r[2]), "=r"(r[3]) : "r"(a));
}
__device__ __forceinline__ void mma16816(float* c, const uint32_t* a, const uint32_t* b) {
    asm volatile(
        "mma.sync.aligned.m16n8k16.row.col.f32.bf16.bf16.f32 "
        "{%0,%1,%2,%3}, {%4,%5,%6,%7}, {%8,%9}, {%0,%1,%2,%3};"
        : "+f"(c[0]), "+f"(c[1]), "+f"(c[2]), "+f"(c[3])
        : "r"(a[0]), "r"(a[1]), "r"(a[2]), "r"(a[3]), "r"(b[0]), "r"(b[1]));
}

// ---------------- fp32 -> bf16 hi/lo split ----------------
__global__ void split_kernel(const float* __restrict__ src,
                             __nv_bfloat16* __restrict__ hi,
                             __nv_bfloat16* __restrict__ lo, int n4) {
    int i = blockIdx.x * blockDim.x + threadIdx.x;
    if (i >= n4) return;
    float4 v = ((const float4*)src)[i];
    __nv_bfloat16 ha = __float2bfloat16_rn(v.x);
    __nv_bfloat16 hb = __float2bfloat16_rn(v.y);
    __nv_bfloat16 hc = __float2bfloat16_rn(v.z);
    __nv_bfloat16 hd = __float2bfloat16_rn(v.w);
    __nv_bfloat16 la = __float2bfloat16_rn(v.x - __bfloat162float(ha));
    __nv_bfloat16 lb = __float2bfloat16_rn(v.y - __bfloat162float(hb));
    __nv_bfloat16 lc = __float2bfloat16_rn(v.z - __bfloat162float(hc));
    __nv_bfloat16 ld = __float2bfloat16_rn(v.w - __bfloat162float(hd));
    __nv_bfloat162 h0; h0.x = ha; h0.y = hb;
    __nv_bfloat162 h1; h1.x = hc; h1.y = hd;
    __nv_bfloat162 l0; l0.x = la; l0.y = lb;
    __nv_bfloat162 l1; l1.x = lc; l1.y = ld;
    ((__nv_bfloat162*)hi)[2 * i] = h0;
    ((__nv_bfloat162*)hi)[2 * i + 1] = h1;
    ((__nv_bfloat162*)lo)[2 * i] = l0;
    ((__nv_bfloat162*)lo)[2 * i + 1] = l1;
}

// ---------------- bf16-split HMMA GEMM ----------------
// C[M,N] = (Ah+Al)[M,K] * (Bh+Bl)[N,K]^T  (3 products, fp32 accum)
// CTA tile 128x128, 8 warps (64x32 each), BK=32, 2-stage cp.async pipeline.
#define BK 32
#define NCH (DIM / BK)      // 32 k-slabs
#define ROWB 80             // padded smem row: 32 bf16 -> 80 bytes (20-bank stride)
#define TILE_B (128 * ROWB) // 10240
#define STG_B (4 * TILE_B)  // 40960
#define GSMEM (2 * STG_B)   // 81920

__global__ __launch_bounds__(256, 1) void gemm_mma(
    const __nv_bfloat16* __restrict__ Ah, const __nv_bfloat16* __restrict__ Al,
    const __nv_bfloat16* __restrict__ Bh, const __nv_bfloat16* __restrict__ Bl,
    float* __restrict__ C) {
    extern __shared__ __align__(128) char smem[];
    const int tid = threadIdx.x;
    const int wid = tid >> 5, lane = tid & 31;
    const int row0 = blockIdx.y * 128, col0 = blockIdx.x * 128;
    const int wm = (wid & 1) * 64, wn = (wid >> 1) * 32;
    const uint32_t sb = s2u(smem);

    const int lr = tid >> 2;   // 0..63
    const int lsg = tid & 3;   // 16B segment

    const __nv_bfloat16* srcs[4] = {Ah, Al, Bh, Bl};

#define LOAD_STAGE(c, s)                                                          \
    {                                                                             \
        uint32_t st_ = sb + (s) * STG_B;                                          \
        _Pragma("unroll") for (int m_ = 0; m_ < 4; m_++) {                        \
            int rbase_ = (m_ < 2) ? row0 : col0;                                  \
            const char* g_ = (const char*)(srcs[m_] +                             \
                (size_t)(rbase_ + lr) * DIM + (c) * BK + lsg * 8);                \
            uint32_t sa_ = st_ + m_ * TILE_B + lr * ROWB + lsg * 16;              \
            cp16(sa_, g_);                                                        \
            cp16(sa_ + 64 * ROWB, g_ + (size_t)64 * DIM * 2);                     \
        }                                                                         \
    }

    float acc[4][4][4];
#pragma unroll
    for (int i = 0; i < 4; i++)
#pragma unroll
        for (int j = 0; j < 4; j++)
#pragma unroll
            for (int u = 0; u < 4; u++) acc[i][j][u] = 0.f;

    LOAD_STAGE(0, 0);
    cp_commit();

    const int ar = lane & 15, ac = lane >> 4;
    const int br = lane & 7, bks = (lane >> 3) & 1, bjj = (lane >> 4) & 1;

    for (int c = 0; c < NCH; c++) {
        if (c < NCH - 1) {
            LOAD_STAGE(c + 1, (c + 1) & 1);
            cp_commit();
            cp_wait<1>();
        } else {
            cp_wait<0>();
        }
        __syncthreads();

        uint32_t st = sb + (c & 1) * STG_B;
#pragma unroll
        for (int ks = 0; ks < 2; ks++) {
            uint32_t ah[4][4], al[4][4];
#pragma unroll
            for (int i = 0; i < 4; i++) {
                uint32_t ad = st + (uint32_t)((wm + i * 16 + ar) * ROWB + (ks * 2 + ac) * 16);
                ldsm4(ah[i], ad);
                ldsm4(al[i], ad + TILE_B);
            }
            uint32_t bh[2][4], bl[2][4];
#pragma unroll
            for (int j2 = 0; j2 < 2; j2++) {
                uint32_t bd = st + 2 * TILE_B +
                              (uint32_t)((wn + j2 * 16 + bjj * 8 + br) * ROWB + (ks * 2 + bks) * 16);
                ldsm4(bh[j2], bd);
                ldsm4(bl[j2], bd + TILE_B);
            }
#pragma unroll
            for (int i = 0; i < 4; i++)
#pragma unroll
                for (int j = 0; j < 4; j++) {
                    const uint32_t* bhf = &bh[j >> 1][(j & 1) * 2];
                    const uint32_t* blf = &bl[j >> 1][(j & 1) * 2];
                    mma16816(acc[i][j], ah[i], bhf);
                    mma16816(acc[i][j], ah[i], blf);
                    mma16816(acc[i][j], al[i], bhf);
                }
        }
        __syncthreads();
    }

    // epilogue: direct fp32 stores (float2)
#pragma unroll
    for (int i = 0; i < 4; i++) {
        int row = row0 + wm + i * 16 + (lane >> 2);
#pragma unroll
        for (int j = 0; j < 4; j++) {
            int col = col0 + wn + j * 8 + (lane & 3) * 2;
            float2 v0 = {acc[i][j][0], acc[i][j][1]};
            float2 v1 = {acc[i][j][2], acc[i][j][3]};
            *(float2*)(C + (size_t)row * DIM + col) = v0;
            *(float2*)(C + (size_t)(row + 8) * DIM + col) = v1;
        }
    }
#undef LOAD_STAGE
}

// ---------------- RoPE ----------------
__global__ void rope_kernel(float* __restrict__ Q, float* __restrict__ K) {
    int idx = blockIdx.x * blockDim.x + threadIdx.x;
    const int total = TT * NH * (HD / 2);
    if (idx >= total) return;
    int i = idx & 31;
    int rem = idx >> 5;
    int h = rem & (NH - 1);
    int t = rem >> 4;

    float invf = powf(10000.0f, -((float)i) / 32.0f);
    float ang = (float)t * invf;
    float s, c;
    sincosf(ang, &s, &c);

    int base = t * DIM + h * HD + 2 * i;
    float q1 = Q[base], q2 = Q[base + 1];
    Q[base]     = q1 * c - q2 * s;
    Q[base + 1] = q1 * s + q2 * c;
    float k1 = K[base], k2 = K[base + 1];
    K[base]     = k1 * c - k2 * s;
    K[base + 1] = k1 * s + k2 * c;
}

// ---------------- attention: one warp per (t, h) ----------------
__global__ __launch_bounds__(128) void attn_kernel(const float* __restrict__ Q,
                                                   const float* __restrict__ K,
                                                   const float* __restrict__ V,
                                                   float* __restrict__ CTX,
                                                   float* __restrict__ full) {
    const int wid = threadIdx.x >> 5, lane = threadIdx.x & 31;
    const int gw = blockIdx.x * 4 + wid;
    const int h = gw & (NH - 1);
    const int t = gw >> 4;

    __shared__ float sq[4][64];
    __shared__ float sw[4][NKEY + 1];
    __shared__ int sp[4][NKEY + 1];

    {
        float2 qv = ((const float2*)(Q + (size_t)t * DIM + h * HD))[lane];
        sq[wid][2 * lane] = qv.x;
        sq[wid][2 * lane + 1] = qv.y;
    }
    __syncwarp();

    float s[3];
    int pos[3];
    bool val[3];
#pragma unroll
    for (int u = 0; u < 3; u++) {
        int kk = lane + 32 * u;
        bool have = (kk < NKEY);
        int p;
        bool v = have;
        if (kk < KS) {
            p = t - WIN + kk;
            v = have && (p >= 0 && p < TT);
        } else {
            p = (kk - KS) * 64;
        }
        float acc = 0.f;
        if (v) {
            const float4* kr = (const float4*)(K + (size_t)p * DIM + h * HD);
            const float4* q4 = (const float4*)sq[wid];
#pragma unroll
            for (int d = 0; d < 16; d++) {
                float4 kv = kr[d], qq = q4[d];
                acc += kv.x * qq.x + kv.y * qq.y + kv.z * qq.z + kv.w * qq.w;
            }
            acc *= 0.125f;
        }
        s[u] = have ? acc : -1e30f;  // invalid-local: logit 0 (zero-padded K)
        pos[u] = p;
        val[u] = v;
    }

    float m = fmaxf(fmaxf(s[0], s[1]), s[2]);
#pragma unroll
    for (int o = 16; o > 0; o >>= 1) m = fmaxf(m, __shfl_xor_sync(0xFFFFFFFFu, m, o));
    float e[3], sum = 0.f;
#pragma unroll
    for (int u = 0; u < 3; u++) {
        e[u] = __expf(s[u] - m) * 0.f + expf(s[u] - m);  // use accurate expf
        sum += e[u];
    }
#pragma unroll
    for (int o = 16; o > 0; o >>= 1) sum += __shfl_xor_sync(0xFFFFFFFFu, sum, o);
    const float inv = 1.f / sum;

    float* rowp = full + ((size_t)h * TT + t) * TT;
#pragma unroll
    for (int u = 0; u < 3; u++) {
        int kk = lane + 32 * u;
        if (kk < NKEY) {
            float w = e[u] * inv;
            sw[wid][kk] = w;
            sp[wid][kk] = val[u] ? pos[u] : -1;
            if (kk < KS) {
                int left = max(t - WIN, 0);
                int right = min(t + WIN + 1, TT);
                int col = left + kk;
                if (col < right) atomicAdd(rowp + col, w);
            } else {
                atomicAdd(rowp + (kk - KS) * 64, w);
            }
        }
    }
    __syncwarp();

    float acc0 = 0.f, acc1 = 0.f;  // dims 2*lane, 2*lane+1
#pragma unroll 1
    for (int i = 0; i < NKEY; i++) {
        int p = sp[wid][i];
        if (p >= 0) {
            float wv = sw[wid][i];
            float2 vv = ((const float2*)(V + (size_t)p * DIM + h * HD))[lane];
            acc0 += wv * vv.x;
            acc1 += wv * vv.y;
        }
    }
    float2 o2 = {acc0, acc1};
    ((float2*)(CTX + (size_t)t * DIM + h * HD))[lane] = o2;
}

// ---------------- kernel_launch ----------------
extern "C" void kernel_launch(void* const* d_in, const int* in_sizes, int n_in,
                              void* d_out, int out_size) {
    const float* x  = (const float*)d_in[0];
    const float* Wq = (const float*)d_in[1];
    const float* Wk = (const float*)d_in[2];
    const float* Wv = (const float*)d_in[3];
    const float* Wo = (const float*)d_in[4];

    float* out  = (float*)d_out;
    float* full = (float*)d_out + (size_t)TT * DIM;

    float *Q, *Kb, *V, *CTX;
    cudaGetSymbolAddress((void**)&Q,   g_Q);
    cudaGetSymbolAddress((void**)&Kb,  g_K);
    cudaGetSymbolAddress((void**)&V,   g_V);
    cudaGetSymbolAddress((void**)&CTX, g_CTX);
    __nv_bfloat16 *xh, *xl, *wh, *wl, *ch, *cl;
    cudaGetSymbolAddress((void**)&xh, g_xh);
    cudaGetSymbolAddress((void**)&xl, g_xl);
    cudaGetSymbolAddress((void**)&wh, g_wh);
    cudaGetSymbolAddress((void**)&wl, g_wl);
    cudaGetSymbolAddress((void**)&ch, g_ch);
    cudaGetSymbolAddress((void**)&cl, g_cl);

    cudaFuncSetAttribute(gemm_mma, cudaFuncAttributeMaxDynamicSharedMemorySize, GSMEM);

    cudaMemsetAsync(full, 0, (size_t)NH * TT * TT * sizeof(float));

    {
        int n4x = TT * DIM / 4;
        int n4w = DIM * DIM / 4;
        split_kernel<<<(n4x + 255) / 256, 256>>>(x, xh, xl, n4x);
        const float* Ws[4] = {Wq, Wk, Wv, Wo};
        for (int i = 0; i < 4; i++)
            split_kernel<<<(n4w + 255) / 256, 256>>>(Ws[i], wh + (size_t)i * DIM * DIM,
                                                     wl + (size_t)i * DIM * DIM, n4w);
    }

    dim3 gg(DIM / 128, TT / 128);  // (8, 16)
    gemm_mma<<<gg, 256, GSMEM>>>(xh, xl, wh + 0 * (size_t)DIM * DIM,
                                 wl + 0 * (size_t)DIM * DIM, Q);
    gemm_mma<<<gg, 256, GSMEM>>>(xh, xl, wh + 1 * (size_t)DIM * DIM,
                                 wl + 1 * (size_t)DIM * DIM, Kb);
    gemm_mma<<<gg, 256, GSMEM>>>(xh, xl, wh + 2 * (size_t)DIM * DIM,
                                 wl + 2 * (size_t)DIM * DIM, V);

    {
        int total = TT * NH * (HD / 2);
        rope_kernel<<<(total + 255) / 256, 256>>>(Q, Kb);
    }

    attn_kernel<<<TT * NH / 4, 128>>>(Q, Kb, V, CTX, full);

    {
        int n4 = TT * DIM / 4;
        split_kernel<<<(n4 + 255) / 256, 256>>>(CTX, ch, cl, n4);
    }
    gemm_mma<<<gg, 256, GSMEM>>>(ch, cl, wh + 3 * (size_t)DIM * DIM,
                                 wl + 3 * (size_t)DIM * DIM, out);
}

// round 5
// speedup vs baseline: 4.8158x; 1.4868x over previous
#include <cuda_runtime.h>
#include <cuda_bf16.h>
#include <math.h>
#include <cstdint>

#define TT 2048
#define DIM 1024
#define NH 16
#define HD 64
#define WIN 16
#define KS 33
#define NG 32
#define NKEY (KS + NG)

// ---------------- scratch (device globals, no allocation) ----------------
__device__ float g_Q[TT * DIM];
__device__ float g_K[TT * DIM];
__device__ float g_V[TT * DIM];
__device__ __nv_bfloat16 g_xh[TT * DIM], g_xl[TT * DIM];
__device__ __nv_bfloat16 g_wh[4][DIM * DIM], g_wl[4][DIM * DIM];
__device__ __nv_bfloat16 g_ch[TT * DIM], g_cl[TT * DIM];

// ---------------- PTX helpers (sm_80-generic only) ----------------
__device__ __forceinline__ uint32_t s2u(const void* p) {
    uint32_t a;
    asm("{ .reg .u64 t; cvta.to.shared.u64 t, %1; cvt.u32.u64 %0, t; }" : "=r"(a) : "l"(p));
    return a;
}
__device__ __forceinline__ void cp16(uint32_t saddr, const void* g) {
    asm volatile("cp.async.cg.shared.global [%0], [%1], 16;" :: "r"(saddr), "l"(g));
}
__device__ __forceinline__ void cp_commit() {
    asm volatile("cp.async.commit_group;" ::: "memory");
}
template <int N>
__device__ __forceinline__ void cp_wait() {
    asm volatile("cp.async.wait_group %0;" :: "n"(N) : "memory");
}
__device__ __forceinline__ void ldsm4(uint32_t* r, uint32_t a) {
    asm volatile("ldmatrix.sync.aligned.m8n8.x4.shared.b16 {%0,%1,%2,%3}, [%4];"
                 : "=r"(r[0]), "=r"(r[1]), "=r"(r[2]), "=r"(r[3]) : "r"(a));
}
__device__ __forceinline__ void mma16816(float* c, const uint32_t* a, const uint32_t* b) {
    asm volatile(
        "mma.sync.aligned.m16n8k16.row.col.f32.bf16.bf16.f32 "
        "{%0,%1,%2,%3}, {%4,%5,%6,%7}, {%8,%9}, {%0,%1,%2,%3};"
        : "+f"(c[0]), "+f"(c[1]), "+f"(c[2]), "+f"(c[3])
        : "r"(a[0]), "r"(a[1]), "r"(a[2]), "r"(a[3]), "r"(b[0]), "r"(b[1]));
}

// ---------------- fp32 -> bf16 hi/lo split ----------------
__device__ __forceinline__ void split4(float4 v, __nv_bfloat162* hi2, __nv_bfloat162* lo2) {
    __nv_bfloat16 ha = __float2bfloat16_rn(v.x);
    __nv_bfloat16 hb = __float2bfloat16_rn(v.y);
    __nv_bfloat16 hc = __float2bfloat16_rn(v.z);
    __nv_bfloat16 hd = __float2bfloat16_rn(v.w);
    __nv_bfloat16 la = __float2bfloat16_rn(v.x - __bfloat162float(ha));
    __nv_bfloat16 lb = __float2bfloat16_rn(v.y - __bfloat162float(hb));
    __nv_bfloat16 lc = __float2bfloat16_rn(v.z - __bfloat162float(hc));
    __nv_bfloat16 ld = __float2bfloat16_rn(v.w - __bfloat162float(hd));
    hi2[0].x = ha; hi2[0].y = hb; hi2[1].x = hc; hi2[1].y = hd;
    lo2[0].x = la; lo2[0].y = lb; lo2[1].x = lc; lo2[1].y = ld;
}

__global__ void split_kernel(const float* __restrict__ src,
                             __nv_bfloat16* __restrict__ hi,
                             __nv_bfloat16* __restrict__ lo, int n4) {
    int i = blockIdx.x * blockDim.x + threadIdx.x;
    if (i >= n4) return;
    float4 v = ((const float4*)src)[i];
    __nv_bfloat162 h2[2], l2[2];
    split4(v, h2, l2);
    ((__nv_bfloat162*)hi)[2 * i] = h2[0];
    ((__nv_bfloat162*)hi)[2 * i + 1] = h2[1];
    ((__nv_bfloat162*)lo)[2 * i] = l2[0];
    ((__nv_bfloat162*)lo)[2 * i + 1] = l2[1];
}

// 4 weight matrices in one launch (blockIdx.y selects matrix)
__global__ void split_w_kernel(const float* __restrict__ W0, const float* __restrict__ W1,
                               const float* __restrict__ W2, const float* __restrict__ W3,
                               __nv_bfloat16* __restrict__ hi, __nv_bfloat16* __restrict__ lo) {
    int m = blockIdx.y;
    const float* src = (m == 0) ? W0 : (m == 1) ? W1 : (m == 2) ? W2 : W3;
    int i = blockIdx.x * blockDim.x + threadIdx.x;  // n4 = DIM*DIM/4 exactly covered
    float4 v = ((const float4*)src)[i];
    __nv_bfloat162 h2[2], l2[2];
    split4(v, h2, l2);
    size_t base = (size_t)m * (DIM * DIM / 2);
    ((__nv_bfloat162*)hi)[base + 2 * i] = h2[0];
    ((__nv_bfloat162*)hi)[base + 2 * i + 1] = h2[1];
    ((__nv_bfloat162*)lo)[base + 2 * i] = l2[0];
    ((__nv_bfloat162*)lo)[base + 2 * i + 1] = l2[1];
}

// ---------------- bf16-split HMMA GEMM (+ optional fused RoPE) ----------------
// C[M, 3x1024] = (Ah+Al)[M,K] * (Bh+Bl)[N,K]^T ; per-128-col-tile output routed
// to C0/C1/C2 by col/1024; rope applied to matrices 0,1 when doRope!=0.
#define BK 32
#define NCH (DIM / BK)
#define ROWB 80
#define TILE_B (128 * ROWB)
#define STG_B (4 * TILE_B)
#define GSMEM (2 * STG_B)

__global__ __launch_bounds__(256, 1) void gemm_mma(
    const __nv_bfloat16* __restrict__ Ah, const __nv_bfloat16* __restrict__ Al,
    const __nv_bfloat16* __restrict__ Bh, const __nv_bfloat16* __restrict__ Bl,
    float* __restrict__ C0, float* __restrict__ C1, float* __restrict__ C2,
    int doRope) {
    extern __shared__ __align__(128) char smem[];
    const int tid = threadIdx.x;
    const int wid = tid >> 5, lane = tid & 31;
    const int row0 = blockIdx.y * 128, col0 = blockIdx.x * 128;
    const int wm = (wid & 1) * 64, wn = (wid >> 1) * 32;
    const uint32_t sb = s2u(smem);

    const int lr = tid >> 2;
    const int lsg = tid & 3;

    const __nv_bfloat16* srcs[4] = {Ah, Al, Bh, Bl};

#define LOAD_STAGE(c, s)                                                          \
    {                                                                             \
        uint32_t st_ = sb + (s) * STG_B;                                          \
        _Pragma("unroll") for (int m_ = 0; m_ < 4; m_++) {                        \
            int rbase_ = (m_ < 2) ? row0 : col0;                                  \
            const char* g_ = (const char*)(srcs[m_] +                             \
                (size_t)(rbase_ + lr) * DIM + (c) * BK + lsg * 8);                \
            uint32_t sa_ = st_ + m_ * TILE_B + lr * ROWB + lsg * 16;              \
            cp16(sa_, g_);                                                        \
            cp16(sa_ + 64 * ROWB, g_ + (size_t)64 * DIM * 2);                     \
        }                                                                         \
    }

    float acc[4][4][4];
#pragma unroll
    for (int i = 0; i < 4; i++)
#pragma unroll
        for (int j = 0; j < 4; j++)
#pragma unroll
            for (int u = 0; u < 4; u++) acc[i][j][u] = 0.f;

    LOAD_STAGE(0, 0);
    cp_commit();

    const int ar = lane & 15, ac = lane >> 4;
    const int br = lane & 7, bks = (lane >> 3) & 1, bjj = (lane >> 4) & 1;

    for (int c = 0; c < NCH; c++) {
        if (c < NCH - 1) {
            LOAD_STAGE(c + 1, (c + 1) & 1);
            cp_commit();
            cp_wait<1>();
        } else {
            cp_wait<0>();
        }
        __syncthreads();

        uint32_t st = sb + (c & 1) * STG_B;
#pragma unroll
        for (int ks = 0; ks < 2; ks++) {
            uint32_t ah[4][4], al[4][4];
#pragma unroll
            for (int i = 0; i < 4; i++) {
                uint32_t ad = st + (uint32_t)((wm + i * 16 + ar) * ROWB + (ks * 2 + ac) * 16);
                ldsm4(ah[i], ad);
                ldsm4(al[i], ad + TILE_B);
            }
            uint32_t bh[2][4], bl[2][4];
#pragma unroll
            for (int j2 = 0; j2 < 2; j2++) {
                uint32_t bd = st + 2 * TILE_B +
                              (uint32_t)((wn + j2 * 16 + bjj * 8 + br) * ROWB + (ks * 2 + bks) * 16);
                ldsm4(bh[j2], bd);
                ldsm4(bl[j2], bd + TILE_B);
            }
#pragma unroll
            for (int i = 0; i < 4; i++)
#pragma unroll
                for (int j = 0; j < 4; j++) {
                    const uint32_t* bhf = &bh[j >> 1][(j & 1) * 2];
                    const uint32_t* blf = &bl[j >> 1][(j & 1) * 2];
                    mma16816(acc[i][j], ah[i], bhf);
                    mma16816(acc[i][j], ah[i], blf);
                    mma16816(acc[i][j], al[i], bhf);
                }
        }
        __syncthreads();
    }

    // epilogue: route by matrix, optional rope, fp32 float2 stores
    const int mat = col0 >> 10;
    float* Cm = (mat == 0) ? C0 : ((mat == 1) ? C1 : C2);
    const bool rope = (doRope != 0) && (mat < 2);
    const int colbase = (col0 & 1023) + wn;

#pragma unroll
    for (int j = 0; j < 4; j++) {
        int colm = colbase + j * 8 + (lane & 3) * 2;
        float invf = 0.f;
        if (rope) {
            int ip = (colm & 63) >> 1;
            invf = powf(10000.0f, -(float)ip * (1.0f / 32.0f));
        }
#pragma unroll
        for (int i = 0; i < 4; i++) {
            int row = row0 + wm + i * 16 + (lane >> 2);
            float2 v0 = {acc[i][j][0], acc[i][j][1]};
            float2 v1 = {acc[i][j][2], acc[i][j][3]};
            if (rope) {
                float s, cc;
                sincosf((float)row * invf, &s, &cc);
                v0 = {v0.x * cc - v0.y * s, v0.x * s + v0.y * cc};
                sincosf((float)(row + 8) * invf, &s, &cc);
                v1 = {v1.x * cc - v1.y * s, v1.x * s + v1.y * cc};
            }
            *(float2*)(Cm + (size_t)row * DIM + colm) = v0;
            *(float2*)(Cm + (size_t)(row + 8) * DIM + colm) = v1;
        }
    }
#undef LOAD_STAGE
}

// ---------------- tiled attention ----------------
// Block = (64-token tile, head). smem: KT transposed [64][129], V [128][68],
// q[8][64], w[8][72]. Warp w handles 8 consecutive t.
#define KTS 129
#define VSTR 68
#define SM_KT 0
#define SM_V (64 * KTS)                 // 8256
#define SM_Q (SM_V + 128 * VSTR)        // 16960
#define SM_W (SM_Q + 8 * 64)            // 17472
#define ATT_SMEM ((SM_W + 8 * 72) * 4)  // 72192 bytes

__global__ __launch_bounds__(256) void attn_kernel(const float* __restrict__ Q,
                                                   const float* __restrict__ K,
                                                   const float* __restrict__ V,
                                                   __nv_bfloat16* __restrict__ CH,
                                                   __nv_bfloat16* __restrict__ CL,
                                                   float* __restrict__ full) {
    extern __shared__ float sm[];
    const int tid = threadIdx.x;
    const int wid = tid >> 5, lane = tid & 31;
    const int t0 = blockIdx.x * 64;
    const int h = blockIdx.y;

    // -------- load K (transposed) and V tiles --------
#pragma unroll
    for (int pass = 0; pass < 8; pass++) {
        int task = tid + pass * 256;
        int r = task >> 4;          // 0..127
        int c4 = task & 15;         // float4 chunk
        int p = (r < 96) ? (t0 - WIN + r) : ((r - 96) * 64);
        float4 kv = {0.f, 0.f, 0.f, 0.f}, vv = {0.f, 0.f, 0.f, 0.f};
        if (p >= 0 && p < TT) {
            const float* base = K + (size_t)p * DIM + h * HD + c4 * 4;
            kv = *(const float4*)base;
            vv = *(const float4*)(V + (size_t)p * DIM + h * HD + c4 * 4);
        }
        int d = c4 * 4;
        sm[SM_KT + (d + 0) * KTS + r] = kv.x;
        sm[SM_KT + (d + 1) * KTS + r] = kv.y;
        sm[SM_KT + (d + 2) * KTS + r] = kv.z;
        sm[SM_KT + (d + 3) * KTS + r] = kv.w;
        *(float4*)&sm[SM_V + r * VSTR + d] = vv;
    }
    __syncthreads();

    float* sq = &sm[SM_Q + wid * 64];
    float* sw = &sm[SM_W + wid * 72];

    for (int it = 0; it < 8; it++) {
        const int t = t0 + wid * 8 + it;

        {
            float2 qv = ((const float2*)(Q + (size_t)t * DIM + h * HD))[lane];
            sq[2 * lane] = qv.x;
            sq[2 * lane + 1] = qv.y;
        }
        __syncwarp();

        // scores: lane-per-key
        int rowi[3];
        bool have[3];
        float sc[3] = {0.f, 0.f, 0.f};
#pragma unroll
        for (int u = 0; u < 3; u++) {
            int kk = u * 32 + lane;
            have[u] = (kk < NKEY);
            rowi[u] = (kk < KS) ? (t - t0 + kk) : (96 + kk - KS);
            if (!have[u]) rowi[u] = 0;
        }
#pragma unroll
        for (int d = 0; d < 64; d++) {
            float qd = sq[d];
            const float* kt = &sm[SM_KT + d * KTS];
            sc[0] += qd * kt[rowi[0]];
            sc[1] += qd * kt[rowi[1]];
            sc[2] += qd * kt[rowi[2]];
        }
        float s0 = have[0] ? sc[0] * 0.125f : -1e30f;
        float s1 = have[1] ? sc[1] * 0.125f : -1e30f;
        float s2 = have[2] ? sc[2] * 0.125f : -1e30f;

        float m = fmaxf(fmaxf(s0, s1), s2);
#pragma unroll
        for (int o = 16; o > 0; o >>= 1) m = fmaxf(m, __shfl_xor_sync(0xFFFFFFFFu, m, o));
        float e0 = expf(s0 - m), e1 = expf(s1 - m), e2 = expf(s2 - m);
        float sum = e0 + e1 + e2;
#pragma unroll
        for (int o = 16; o > 0; o >>= 1) sum += __shfl_xor_sync(0xFFFFFFFFu, sum, o);
        const float inv = 1.f / sum;

        // weights -> smem + scatter into full
        float* rowp = full + ((size_t)h * TT + t) * TT;
        const int left = max(t - WIN, 0);
        const int right = min(t + WIN + 1, TT);
        float ee[3] = {e0, e1, e2};
#pragma unroll
        for (int u = 0; u < 3; u++) {
            int kk = u * 32 + lane;
            if (kk < NKEY) {
                float w = ee[u] * inv;
                sw[kk] = w;
                if (kk < KS) {
                    int col = left + kk;
                    if (col < right) atomicAdd(rowp + col, w);
                } else {
                    atomicAdd(rowp + (kk - KS) * 64, w);
                }
            }
        }
        __syncwarp();

        // ctx: lane owns dims (2*lane, 2*lane+1)
        float a0 = 0.f, a1 = 0.f;
#pragma unroll
        for (int i = 0; i < NKEY; i++) {
            int r = (i < KS) ? (t - t0 + i) : (96 + i - KS);
            float wv = sw[i];
            float2 vv = *(float2*)&sm[SM_V + r * VSTR + 2 * lane];
            a0 += wv * vv.x;
            a1 += wv * vv.y;
        }

        // write bf16 hi/lo split of ctx
        __nv_bfloat16 h0 = __float2bfloat16_rn(a0);
        __nv_bfloat16 h1 = __float2bfloat16_rn(a1);
        __nv_bfloat16 l0 = __float2bfloat16_rn(a0 - __bfloat162float(h0));
        __nv_bfloat16 l1 = __float2bfloat16_rn(a1 - __bfloat162float(h1));
        size_t co = ((size_t)t * DIM + h * HD) / 2 + lane;
        __nv_bfloat162 hh; hh.x = h0; hh.y = h1;
        __nv_bfloat162 ll; ll.x = l0; ll.y = l1;
        ((__nv_bfloat162*)CH)[co] = hh;
        ((__nv_bfloat162*)CL)[co] = ll;
        __syncwarp();
    }
}

// ---------------- kernel_launch ----------------
extern "C" void kernel_launch(void* const* d_in, const int* in_sizes, int n_in,
                              void* d_out, int out_size) {
    const float* x  = (const float*)d_in[0];
    const float* Wq = (const float*)d_in[1];
    const float* Wk = (const float*)d_in[2];
    const float* Wv = (const float*)d_in[3];
    const float* Wo = (const float*)d_in[4];

    float* out  = (float*)d_out;
    float* full = (float*)d_out + (size_t)TT * DIM;

    float *Q, *Kb, *V;
    cudaGetSymbolAddress((void**)&Q,  g_Q);
    cudaGetSymbolAddress((void**)&Kb, g_K);
    cudaGetSymbolAddress((void**)&V,  g_V);
    __nv_bfloat16 *xh, *xl, *wh, *wl, *ch, *cl;
    cudaGetSymbolAddress((void**)&xh, g_xh);
    cudaGetSymbolAddress((void**)&xl, g_xl);
    cudaGetSymbolAddress((void**)&wh, g_wh);
    cudaGetSymbolAddress((void**)&wl, g_wl);
    cudaGetSymbolAddress((void**)&ch, g_ch);
    cudaGetSymbolAddress((void**)&cl, g_cl);

    cudaFuncSetAttribute(gemm_mma, cudaFuncAttributeMaxDynamicSharedMemorySize, GSMEM);
    cudaFuncSetAttribute(attn_kernel, cudaFuncAttributeMaxDynamicSharedMemorySize, ATT_SMEM);

    cudaMemsetAsync(full, 0, (size_t)NH * TT * TT * sizeof(float));

    {
        int n4x = TT * DIM / 4;
        split_kernel<<<(n4x + 255) / 256, 256>>>(x, xh, xl, n4x);
        dim3 gw(DIM * DIM / 4 / 256, 4);
        split_w_kernel<<<gw, 256>>>(Wq, Wk, Wv, Wo, wh, wl);
    }

    // fused QKV projection + RoPE (N = 3072)
    {
        dim3 gg(3 * DIM / 128, TT / 128);  // (24, 16)
        gemm_mma<<<gg, 256, GSMEM>>>(xh, xl, wh, wl, Q, Kb, V, 1);
    }

    // tiled attention (writes ctx bf16-split + full scatter)
    {
        dim3 ga(TT / 64, NH);  // (32, 16)
        attn_kernel<<<ga, 256, ATT_SMEM>>>(Q, Kb, V, ch, cl, full);
    }

    // output projection
    {
        dim3 gg(DIM / 128, TT / 128);  // (8, 16)
        gemm_mma<<<gg, 256, GSMEM>>>(ch, cl, wh + 3 * (size_t)DIM * DIM,
                                     wl + 3 * (size_t)DIM * DIM, out, out, out, 0);
    }
}

// round 7
// speedup vs baseline: 7.4997x; 1.5573x over previous
#include <cuda_runtime.h>
#include <cuda_bf16.h>
#include <cuda_fp16.h>
#include <math.h>
#include <cstdint>

#define TT 2048
#define DIM 1024
#define NH 16
#define HD 64
#define WIN 16
#define KS 33
#define NG 32
#define NKEY (KS + NG)

// ---------------- scratch (device globals, no allocation) ----------------
__device__ float g_Q[TT * DIM];
__device__ float g_K[TT * DIM];
__device__ float g_V[TT * DIM];
__device__ __half g_xf[TT * DIM];
__device__ __half g_wf[3 * DIM * DIM];
__device__ __nv_bfloat16 g_woh[DIM * DIM], g_wol[DIM * DIM];
__device__ __nv_bfloat16 g_ch[TT * DIM], g_cl[TT * DIM];

// ---------------- PTX helpers (sm_80-generic only) ----------------
__device__ __forceinline__ uint32_t s2u(const void* p) {
    uint32_t a;
    asm("{ .reg .u64 t; cvta.to.shared.u64 t, %1; cvt.u32.u64 %0, t; }" : "=r"(a) : "l"(p));
    return a;
}
__device__ __forceinline__ void cp16(uint32_t saddr, const void* g) {
    asm volatile("cp.async.cg.shared.global [%0], [%1], 16;" :: "r"(saddr), "l"(g));
}
__device__ __forceinline__ void cp_commit() {
    asm volatile("cp.async.commit_group;" ::: "memory");
}
template <int N>
__device__ __forceinline__ void cp_wait() {
    asm volatile("cp.async.wait_group %0;" :: "n"(N) : "memory");
}
__device__ __forceinline__ void ldsm4(uint32_t* r, uint32_t a) {
    asm volatile("ldmatrix.sync.aligned.m8n8.x4.shared.b16 {%0,%1,%2,%3}, [%4];"
                 : "=r"(r[0]), "=r"(r[1]), "=r"(r[2]), "=r"(r[3]) : "r"(a));
}
__device__ __forceinline__ void mma_bf16(float* c, const uint32_t* a, const uint32_t* b) {
    asm volatile(
        "mma.sync.aligned.m16n8k16.row.col.f32.bf16.bf16.f32 "
        "{%0,%1,%2,%3}, {%4,%5,%6,%7}, {%8,%9}, {%0,%1,%2,%3};"
        : "+f"(c[0]), "+f"(c[1]), "+f"(c[2]), "+f"(c[3])
        : "r"(a[0]), "r"(a[1]), "r"(a[2]), "r"(a[3]), "r"(b[0]), "r"(b[1]));
}
__device__ __forceinline__ void mma_fp16(float* c, const uint32_t* a, const uint32_t* b) {
    asm volatile(
        "mma.sync.aligned.m16n8k16.row.col.f32.f16.f16.f32 "
        "{%0,%1,%2,%3}, {%4,%5,%6,%7}, {%8,%9}, {%0,%1,%2,%3};"
        : "+f"(c[0]), "+f"(c[1]), "+f"(c[2]), "+f"(c[3])
        : "r"(a[0]), "r"(a[1]), "r"(a[2]), "r"(a[3]), "r"(b[0]), "r"(b[1]));
}

// ---------------- conversions ----------------
__global__ void conv_f16(const float* __restrict__ src, __half* __restrict__ dst, int n4) {
    int i = blockIdx.x * blockDim.x + threadIdx.x;
    if (i >= n4) return;
    float4 v = ((const float4*)src)[i];
    __half2 a = __floats2half2_rn(v.x, v.y);
    __half2 b = __floats2half2_rn(v.z, v.w);
    ((__half2*)dst)[2 * i] = a;
    ((__half2*)dst)[2 * i + 1] = b;
}

__global__ void conv_w_f16(const float* __restrict__ W0, const float* __restrict__ W1,
                           const float* __restrict__ W2, __half* __restrict__ dst) {
    int m = blockIdx.y;
    const float* src = (m == 0) ? W0 : (m == 1) ? W1 : W2;
    int i = blockIdx.x * blockDim.x + threadIdx.x;
    float4 v = ((const float4*)src)[i];
    __half2 a = __floats2half2_rn(v.x, v.y);
    __half2 b = __floats2half2_rn(v.z, v.w);
    size_t base = (size_t)m * (DIM * DIM / 2);
    ((__half2*)dst)[base + 2 * i] = a;
    ((__half2*)dst)[base + 2 * i + 1] = b;
}

__global__ void split_bf16(const float* __restrict__ src,
                           __nv_bfloat16* __restrict__ hi,
                           __nv_bfloat16* __restrict__ lo, int n4) {
    int i = blockIdx.x * blockDim.x + threadIdx.x;
    if (i >= n4) return;
    float4 v = ((const float4*)src)[i];
    __nv_bfloat16 ha = __float2bfloat16_rn(v.x), hb = __float2bfloat16_rn(v.y);
    __nv_bfloat16 hc = __float2bfloat16_rn(v.z), hd = __float2bfloat16_rn(v.w);
    __nv_bfloat16 la = __float2bfloat16_rn(v.x - __bfloat162float(ha));
    __nv_bfloat16 lb = __float2bfloat16_rn(v.y - __bfloat162float(hb));
    __nv_bfloat16 lc = __float2bfloat16_rn(v.z - __bfloat162float(hc));
    __nv_bfloat16 ld = __float2bfloat16_rn(v.w - __bfloat162float(hd));
    __nv_bfloat162 h0, h1, l0, l1;
    h0.x = ha; h0.y = hb; h1.x = hc; h1.y = hd;
    l0.x = la; l0.y = lb; l1.x = lc; l1.y = ld;
    ((__nv_bfloat162*)hi)[2 * i] = h0;
    ((__nv_bfloat162*)hi)[2 * i + 1] = h1;
    ((__nv_bfloat162*)lo)[2 * i] = l0;
    ((__nv_bfloat162*)lo)[2 * i + 1] = l1;
}

// ---------------- shared rope epilogue ----------------
__device__ __forceinline__ void gemm_epilogue(float acc[4][4][4], int row0, int col0,
                                              int wm, int wn, int lane,
                                              float* C0, float* C1, float* C2, int doRope) {
    const int mat = col0 >> 10;
    float* Cm = (mat == 0) ? C0 : ((mat == 1) ? C1 : C2);
    const bool rope = (doRope != 0) && (mat < 2);
    const int colbase = (col0 & 1023) + wn;
#pragma unroll
    for (int j = 0; j < 4; j++) {
        int colm = colbase + j * 8 + (lane & 3) * 2;
        float invf = 0.f;
        if (rope) {
            int ip = (colm & 63) >> 1;
            invf = powf(10000.0f, -(float)ip * (1.0f / 32.0f));
        }
#pragma unroll
        for (int i = 0; i < 4; i++) {
            int row = row0 + wm + i * 16 + (lane >> 2);
            float2 v0 = {acc[i][j][0], acc[i][j][1]};
            float2 v1 = {acc[i][j][2], acc[i][j][3]};
            if (rope) {
                float s, cc;
                sincosf((float)row * invf, &s, &cc);
                v0 = {v0.x * cc - v0.y * s, v0.x * s + v0.y * cc};
                sincosf((float)(row + 8) * invf, &s, &cc);
                v1 = {v1.x * cc - v1.y * s, v1.x * s + v1.y * cc};
            }
            *(float2*)(Cm + (size_t)row * DIM + colm) = v0;
            *(float2*)(Cm + (size_t)(row + 8) * DIM + colm) = v1;
        }
    }
}

// ---------------- fp16 single-product HMMA GEMM (+fused RoPE) ----------------
#define BK 32
#define NCH (DIM / BK)
#define RB16 80
#define T16 (128 * RB16)     // 10240
#define STG16 (2 * T16)      // 20480
#define GS16 (2 * STG16)     // 40960

__global__ __launch_bounds__(256) void gemm_f16(
    const __half* __restrict__ Af, const __half* __restrict__ Bf,
    float* __restrict__ C0, float* __restrict__ C1, float* __restrict__ C2,
    int doRope) {
    extern __shared__ __align__(128) char smem[];
    const int tid = threadIdx.x;
    const int wid = tid >> 5, lane = tid & 31;
    const int row0 = blockIdx.y * 128, col0 = blockIdx.x * 128;
    const int wm = (wid & 1) * 64, wn = (wid >> 1) * 32;
    const uint32_t sb = s2u(smem);
    const int lr = tid >> 2, lsg = tid & 3;

#define LOAD16(c, s)                                                               \
    {                                                                              \
        uint32_t st_ = sb + (s) * STG16;                                           \
        _Pragma("unroll") for (int m_ = 0; m_ < 2; m_++) {                         \
            const __half* src_ = m_ ? Bf : Af;                                     \
            int rbase_ = m_ ? col0 : row0;                                         \
            const char* g_ = (const char*)(src_ +                                  \
                (size_t)(rbase_ + lr) * DIM + (c) * BK + lsg * 8);                 \
            uint32_t sa_ = st_ + m_ * T16 + lr * RB16 + lsg * 16;                  \
            cp16(sa_, g_);                                                         \
            cp16(sa_ + 64 * RB16, g_ + (size_t)64 * DIM * 2);                      \
        }                                                                          \
    }

    float acc[4][4][4];
#pragma unroll
    for (int i = 0; i < 4; i++)
#pragma unroll
        for (int j = 0; j < 4; j++)
#pragma unroll
            for (int u = 0; u < 4; u++) acc[i][j][u] = 0.f;

    LOAD16(0, 0);
    cp_commit();

    const int ar = lane & 15, ac = lane >> 4;
    const int br = lane & 7, bks = (lane >> 3) & 1, bjj = (lane >> 4) & 1;

    for (int c = 0; c < NCH; c++) {
        if (c < NCH - 1) {
            LOAD16(c + 1, (c + 1) & 1);
            cp_commit();
            cp_wait<1>();
        } else {
            cp_wait<0>();
        }
        __syncthreads();

        uint32_t st = sb + (c & 1) * STG16;
#pragma unroll
        for (int ks = 0; ks < 2; ks++) {
            uint32_t a[4][4];
#pragma unroll
            for (int i = 0; i < 4; i++) {
                uint32_t ad = st + (uint32_t)((wm + i * 16 + ar) * RB16 + (ks * 2 + ac) * 16);
                ldsm4(a[i], ad);
            }
            uint32_t b[2][4];
#pragma unroll
            for (int j2 = 0; j2 < 2; j2++) {
                uint32_t bd = st + T16 +
                              (uint32_t)((wn + j2 * 16 + bjj * 8 + br) * RB16 + (ks * 2 + bks) * 16);
                ldsm4(b[j2], bd);
            }
#pragma unroll
            for (int i = 0; i < 4; i++)
#pragma unroll
                for (int j = 0; j < 4; j++)
                    mma_fp16(acc[i][j], a[i], &b[j >> 1][(j & 1) * 2]);
        }
        __syncthreads();
    }
    gemm_epilogue(acc, row0, col0, wm, wn, lane, C0, C1, C2, doRope);
#undef LOAD16
}

// ---------------- split-bf16 3-product GEMM (out projection) ----------------
#define ROWB 80
#define TILE_B (128 * ROWB)
#define STG_B (4 * TILE_B)
#define GSMEM (2 * STG_B)

__global__ __launch_bounds__(256) void gemm_bf16s(
    const __nv_bfloat16* __restrict__ Ah, const __nv_bfloat16* __restrict__ Al,
    const __nv_bfloat16* __restrict__ Bh, const __nv_bfloat16* __restrict__ Bl,
    float* __restrict__ C) {
    extern __shared__ __align__(128) char smem[];
    const int tid = threadIdx.x;
    const int wid = tid >> 5, lane = tid & 31;
    const int row0 = blockIdx.y * 128, col0 = blockIdx.x * 128;
    const int wm = (wid & 1) * 64, wn = (wid >> 1) * 32;
    const uint32_t sb = s2u(smem);
    const int lr = tid >> 2, lsg = tid & 3;
    const __nv_bfloat16* srcs[4] = {Ah, Al, Bh, Bl};

#define LOADB(c, s)                                                                \
    {                                                                              \
        uint32_t st_ = sb + (s) * STG_B;                                           \
        _Pragma("unroll") for (int m_ = 0; m_ < 4; m_++) {                         \
            int rbase_ = (m_ < 2) ? row0 : col0;                                   \
            const char* g_ = (const char*)(srcs[m_] +                              \
                (size_t)(rbase_ + lr) * DIM + (c) * BK + lsg * 8);                 \
            uint32_t sa_ = st_ + m_ * TILE_B + lr * ROWB + lsg * 16;               \
            cp16(sa_, g_);                                                         \
            cp16(sa_ + 64 * ROWB, g_ + (size_t)64 * DIM * 2);                      \
        }                                                                          \
    }

    float acc[4][4][4];
#pragma unroll
    for (int i = 0; i < 4; i++)
#pragma unroll
        for (int j = 0; j < 4; j++)
#pragma unroll
            for (int u = 0; u < 4; u++) acc[i][j][u] = 0.f;

    LOADB(0, 0);
    cp_commit();

    const int ar = lane & 15, ac = lane >> 4;
    const int br = lane & 7, bks = (lane >> 3) & 1, bjj = (lane >> 4) & 1;

    for (int c = 0; c < NCH; c++) {
        if (c < NCH - 1) {
            LOADB(c + 1, (c + 1) & 1);
            cp_commit();
            cp_wait<1>();
        } else {
            cp_wait<0>();
        }
        __syncthreads();

        uint32_t st = sb + (c & 1) * STG_B;
#pragma unroll
        for (int ks = 0; ks < 2; ks++) {
            uint32_t ah[4][4], al[4][4];
#pragma unroll
            for (int i = 0; i < 4; i++) {
                uint32_t ad = st + (uint32_t)((wm + i * 16 + ar) * ROWB + (ks * 2 + ac) * 16);
                ldsm4(ah[i], ad);
                ldsm4(al[i], ad + TILE_B);
            }
            uint32_t bh[2][4], bl[2][4];
#pragma unroll
            for (int j2 = 0; j2 < 2; j2++) {
                uint32_t bd = st + 2 * TILE_B +
                              (uint32_t)((wn + j2 * 16 + bjj * 8 + br) * ROWB + (ks * 2 + bks) * 16);
                ldsm4(bh[j2], bd);
                ldsm4(bl[j2], bd + TILE_B);
            }
#pragma unroll
            for (int i = 0; i < 4; i++)
#pragma unroll
                for (int j = 0; j < 4; j++) {
                    const uint32_t* bhf = &bh[j >> 1][(j & 1) * 2];
                    const uint32_t* blf = &bl[j >> 1][(j & 1) * 2];
                    mma_bf16(acc[i][j], ah[i], bhf);
                    mma_bf16(acc[i][j], ah[i], blf);
                    mma_bf16(acc[i][j], al[i], bhf);
                }
        }
        __syncthreads();
    }
    gemm_epilogue(acc, row0, col0, wm, wn, lane, C, C, C, 0);
#undef LOADB
}

// ---------------- tiled attention (zeroing of `full` fused in) ----------------
#define KVS 68
#define SK 0
#define SV (128 * KVS)                  // 8704
#define SQ (SV + 128 * KVS)             // 17408
#define SWL (SQ + 64 * 64)              // 21504
#define SWG (SWL + 8 * 8 * 40)          // 24064
#define ATT_FLOATS (SWG + 8 * 8 * 32)   // 26112
#define ATT_SMEM (ATT_FLOATS * 4)       // 104448 bytes

__global__ __launch_bounds__(256) void attn_kernel(const float* __restrict__ Q,
                                                   const float* __restrict__ K,
                                                   const float* __restrict__ V,
                                                   __nv_bfloat16* __restrict__ CH,
                                                   __nv_bfloat16* __restrict__ CL,
                                                   float* __restrict__ full) {
    extern __shared__ float sm[];
    const int tid = threadIdx.x;
    const int wid = tid >> 5, lane = tid & 31;
    const int t0 = blockIdx.x * 64;
    const int h = blockIdx.y;

    // load K/V rows: 0..95 = window [t0-16, t0+79], 96..127 = globals
#pragma unroll
    for (int pass = 0; pass < 8; pass++) {
        int task = tid + pass * 256;
        int r = task >> 4;
        int c4 = task & 15;
        int p = (r < 96) ? (t0 - WIN + r) : ((r - 96) * 64);
        float4 kv = {0.f, 0.f, 0.f, 0.f}, vv = {0.f, 0.f, 0.f, 0.f};
        if (p >= 0 && p < TT) {
            kv = *(const float4*)(K + (size_t)p * DIM + h * HD + c4 * 4);
            vv = *(const float4*)(V + (size_t)p * DIM + h * HD + c4 * 4);
        }
        *(float4*)&sm[SK + r * KVS + c4 * 4] = kv;
        *(float4*)&sm[SV + r * KVS + c4 * 4] = vv;
    }
    // load Q rows
#pragma unroll
    for (int pass = 0; pass < 4; pass++) {
        int task = tid + pass * 256;
        int tt = task >> 4;
        int c4 = task & 15;
        *(float4*)&sm[SQ + tt * 64 + c4 * 4] =
            *(const float4*)(Q + (size_t)(t0 + tt) * DIM + h * HD + c4 * 4);
    }
    __syncthreads();

    // phase 1: scores + softmax + scatter (+zero full rows)
    for (int it = 0; it < 8; it++) {
        const int trel = wid * 8 + it;
        const int t = t0 + trel;
        float* rowp = full + ((size_t)h * TT + t) * TT;

        // zero this row of `full`
        float4 z4 = {0.f, 0.f, 0.f, 0.f};
#pragma unroll
        for (int z = 0; z < 16; z++) *(float4*)(rowp + (z * 32 + lane) * 4) = z4;

        // scores: lane-per-key
        int rowi[3];
        bool have[3];
        float sc[3] = {0.f, 0.f, 0.f};
#pragma unroll
        for (int u = 0; u < 3; u++) {
            int kk = u * 32 + lane;
            have[u] = (kk < NKEY);
            int r = (kk < KS) ? (trel + kk) : (96 + kk - KS);
            rowi[u] = have[u] ? r : 0;
        }
#pragma unroll
        for (int j = 0; j < 16; j++) {
            float4 q4 = *(float4*)&sm[SQ + trel * 64 + j * 4];
#pragma unroll
            for (int u = 0; u < 3; u++) {
                float4 kv = *(float4*)&sm[SK + rowi[u] * KVS + j * 4];
                sc[u] += kv.x * q4.x + kv.y * q4.y + kv.z * q4.z + kv.w * q4.w;
            }
        }
        float s0 = have[0] ? sc[0] * 0.125f : -1e30f;
        float s1 = have[1] ? sc[1] * 0.125f : -1e30f;
        float s2 = have[2] ? sc[2] * 0.125f : -1e30f;

        float m = fmaxf(fmaxf(s0, s1), s2);
#pragma unroll
        for (int o = 16; o > 0; o >>= 1) m = fmaxf(m, __shfl_xor_sync(0xFFFFFFFFu, m, o));
        float e0 = expf(s0 - m), e1 = expf(s1 - m), e2 = expf(s2 - m);
        float sum = e0 + e1 + e2;
#pragma unroll
        for (int o = 16; o > 0; o >>= 1) sum += __shfl_xor_sync(0xFFFFFFFFu, sum, o);
        const float inv = 1.f / sum;

        // zero w slots
        float* swl = &sm[SWL + wid * 320 + it * 40];
        float* swg = &sm[SWG + wid * 256 + it * 32];
        if (lane < 40) swl[lane] = 0.f;
        if (lane < 8) swl[lane + 32] = 0.f;
        swg[lane] = 0.f;
        __syncwarp();

        const int left = max(t - WIN, 0);
        const int right = min(t + WIN + 1, TT);
        float ee[3] = {e0, e1, e2};
#pragma unroll
        for (int u = 0; u < 3; u++) {
            int kk = u * 32 + lane;
            if (kk < NKEY) {
                float w = ee[u] * inv;
                if (kk < KS) {
                    swl[it + kk] = w;
                    int col = left + kk;
                    if (col < right) atomicAdd(rowp + col, w);
                } else {
                    swg[kk - KS] = w;
                    atomicAdd(rowp + (kk - KS) * 64, w);
                }
            }
        }
        __syncwarp();
    }

    // phase 2: ctx register tile (8 t's per warp, stream V rows once)
    float a0[8], a1[8];
#pragma unroll
    for (int it = 0; it < 8; it++) { a0[it] = 0.f; a1[it] = 0.f; }

    const float* swlb = &sm[SWL + wid * 320];
    const float* swgb = &sm[SWG + wid * 256];
#pragma unroll 4
    for (int j = 0; j < 40; j++) {
        int r = wid * 8 + j;
        float2 v2 = *(float2*)&sm[SV + r * KVS + 2 * lane];
#pragma unroll
        for (int it = 0; it < 8; it++) {
            float w = swlb[it * 40 + j];
            a0[it] += w * v2.x;
            a1[it] += w * v2.y;
        }
    }
#pragma unroll 4
    for (int g = 0; g < 32; g++) {
        float2 v2 = *(float2*)&sm[SV + (96 + g) * KVS + 2 * lane];
#pragma unroll
        for (int it = 0; it < 8; it++) {
            float w = swgb[it * 32 + g];
            a0[it] += w * v2.x;
            a1[it] += w * v2.y;
        }
    }

#pragma unroll
    for (int it = 0; it < 8; it++) {
        int t = t0 + wid * 8 + it;
        __nv_bfloat16 h0 = __float2bfloat16_rn(a0[it]);
        __nv_bfloat16 h1 = __float2bfloat16_rn(a1[it]);
        __nv_bfloat16 l0 = __float2bfloat16_rn(a0[it] - __bfloat162float(h0));
        __nv_bfloat16 l1 = __float2bfloat16_rn(a1[it] - __bfloat162float(h1));
        size_t co = ((size_t)t * DIM + h * HD) / 2 + lane;
        __nv_bfloat162 hh, ll;
        hh.x = h0; hh.y = h1;
        ll.x = l0; ll.y = l1;
        ((__nv_bfloat162*)CH)[co] = hh;
        ((__nv_bfloat162*)CL)[co] = ll;
    }
}

// ---------------- kernel_launch ----------------
extern "C" void kernel_launch(void* const* d_in, const int* in_sizes, int n_in,
                              void* d_out, int out_size) {
    const float* x  = (const float*)d_in[0];
    const float* Wq = (const float*)d_in[1];
    const float* Wk = (const float*)d_in[2];
    const float* Wv = (const float*)d_in[3];
    const float* Wo = (const float*)d_in[4];

    float* out  = (float*)d_out;
    float* full = (float*)d_out + (size_t)TT * DIM;

    float *Q, *Kb, *V;
    cudaGetSymbolAddress((void**)&Q,  g_Q);
    cudaGetSymbolAddress((void**)&Kb, g_K);
    cudaGetSymbolAddress((void**)&V,  g_V);
    __half *xf, *wf;
    cudaGetSymbolAddress((void**)&xf, g_xf);
    cudaGetSymbolAddress((void**)&wf, g_wf);
    __nv_bfloat16 *woh, *wol, *ch, *cl;
    cudaGetSymbolAddress((void**)&woh, g_woh);
    cudaGetSymbolAddress((void**)&wol, g_wol);
    cudaGetSymbolAddress((void**)&ch, g_ch);
    cudaGetSymbolAddress((void**)&cl, g_cl);

    cudaFuncSetAttribute(gemm_f16, cudaFuncAttributeMaxDynamicSharedMemorySize, GS16);
    cudaFuncSetAttribute(gemm_bf16s, cudaFuncAttributeMaxDynamicSharedMemorySize, GSMEM);
    cudaFuncSetAttribute(attn_kernel, cudaFuncAttributeMaxDynamicSharedMemorySize, ATT_SMEM);

    // conversions
    {
        int n4x = TT * DIM / 4;
        conv_f16<<<(n4x + 255) / 256, 256>>>(x, xf, n4x);
        dim3 gw(DIM * DIM / 4 / 256, 3);
        conv_w_f16<<<gw, 256>>>(Wq, Wk, Wv, wf);
        int n4w = DIM * DIM / 4;
        split_bf16<<<(n4w + 255) / 256, 256>>>(Wo, woh, wol, n4w);
    }

    // fused QKV projection + RoPE (fp16 single product)
    {
        dim3 gg(3 * DIM / 128, TT / 128);  // (24, 16)
        gemm_f16<<<gg, 256, GS16>>>(xf, wf, Q, Kb, V, 1);
    }

    // tiled attention (zeroes `full` rows, scatters, writes ctx bf16-split)
    {
        dim3 ga(TT / 64, NH);  // (32, 16)
        attn_kernel<<<ga, 256, ATT_SMEM>>>(Q, Kb, V, ch, cl, full);
    }

    // output projection (split-bf16, 3 products)
    {
        dim3 gg(DIM / 128, TT / 128);  // (8, 16)
        gemm_bf16s<<<gg, 256, GSMEM>>>(ch, cl, woh, wol, out);
    }
}

// round 8
// speedup vs baseline: 8.5119x; 1.1350x over previous
#include <cuda_runtime.h>
#include <cuda_bf16.h>
#include <cuda_fp16.h>
#include <math.h>
#include <cstdint>

#define TT 2048
#define DIM 1024
#define NH 16
#define HD 64
#define WIN 16
#define KS 33
#define NG 32
#define NKEY (KS + NG)

// ---------------- scratch (device globals, no allocation) ----------------
__device__ float g_Q[TT * DIM];
__device__ float g_K[TT * DIM];
__device__ float g_V[TT * DIM];
__device__ __half g_xf[TT * DIM];
__device__ __half g_wf[4 * DIM * DIM];
__device__ __half g_cf[TT * DIM];

// ---------------- PTX helpers (sm_80-generic only) ----------------
__device__ __forceinline__ uint32_t s2u(const void* p) {
    uint32_t a;
    asm("{ .reg .u64 t; cvta.to.shared.u64 t, %1; cvt.u32.u64 %0, t; }" : "=r"(a) : "l"(p));
    return a;
}
__device__ __forceinline__ void cp16(uint32_t saddr, const void* g) {
    asm volatile("cp.async.cg.shared.global [%0], [%1], 16;" :: "r"(saddr), "l"(g));
}
__device__ __forceinline__ void cp_commit() {
    asm volatile("cp.async.commit_group;" ::: "memory");
}
template <int N>
__device__ __forceinline__ void cp_wait() {
    asm volatile("cp.async.wait_group %0;" :: "n"(N) : "memory");
}
__device__ __forceinline__ void ldsm4(uint32_t* r, uint32_t a) {
    asm volatile("ldmatrix.sync.aligned.m8n8.x4.shared.b16 {%0,%1,%2,%3}, [%4];"
                 : "=r"(r[0]), "=r"(r[1]), "=r"(r[2]), "=r"(r[3]) : "r"(a));
}
__device__ __forceinline__ void mma_fp16(float* c, const uint32_t* a, const uint32_t* b) {
    asm volatile(
        "mma.sync.aligned.m16n8k16.row.col.f32.f16.f16.f32 "
        "{%0,%1,%2,%3}, {%4,%5,%6,%7}, {%8,%9}, {%0,%1,%2,%3};"
        : "+f"(c[0]), "+f"(c[1]), "+f"(c[2]), "+f"(c[3])
        : "r"(a[0]), "r"(a[1]), "r"(a[2]), "r"(a[3]), "r"(b[0]), "r"(b[1]));
}

// ---------------- conversions ----------------
__global__ void conv_f16(const float* __restrict__ src, __half* __restrict__ dst, int n4) {
    int i = blockIdx.x * blockDim.x + threadIdx.x;
    if (i >= n4) return;
    float4 v = ((const float4*)src)[i];
    ((__half2*)dst)[2 * i] = __floats2half2_rn(v.x, v.y);
    ((__half2*)dst)[2 * i + 1] = __floats2half2_rn(v.z, v.w);
}

__global__ void conv_w_f16(const float* __restrict__ W0, const float* __restrict__ W1,
                           const float* __restrict__ W2, const float* __restrict__ W3,
                           __half* __restrict__ dst) {
    int m = blockIdx.y;
    const float* src = (m == 0) ? W0 : (m == 1) ? W1 : (m == 2) ? W2 : W3;
    int i = blockIdx.x * blockDim.x + threadIdx.x;
    float4 v = ((const float4*)src)[i];
    size_t base = (size_t)m * (DIM * DIM / 2);
    ((__half2*)dst)[base + 2 * i] = __floats2half2_rn(v.x, v.y);
    ((__half2*)dst)[base + 2 * i + 1] = __floats2half2_rn(v.z, v.w);
}

// ---------------- fp16 HMMA GEMM, 3-stage pipeline, fused RoPE ----------------
#define BK 32
#define NCH (DIM / BK)
#define RB16 80
#define T16 (128 * RB16)     // 10240 bytes per operand tile
#define STG16 (2 * T16)      // 20480 bytes per stage
#define GS16 (3 * STG16)     // 61440

__global__ __launch_bounds__(256) void gemm_f16(
    const __half* __restrict__ Af, const __half* __restrict__ Bf,
    float* __restrict__ C0, float* __restrict__ C1, float* __restrict__ C2,
    int doRope) {
    extern __shared__ __align__(128) char smem[];
    const int tid = threadIdx.x;
    const int wid = tid >> 5, lane = tid & 31;
    const int row0 = blockIdx.y * 128, col0 = blockIdx.x * 128;
    const int wm = (wid & 1) * 64, wn = (wid >> 1) * 32;
    const uint32_t sb = s2u(smem);
    const int lr = tid >> 2, lsg = tid & 3;

#define LOAD16(c, s)                                                               \
    {                                                                              \
        uint32_t st_ = sb + (s) * STG16;                                           \
        _Pragma("unroll") for (int m_ = 0; m_ < 2; m_++) {                         \
            const __half* src_ = m_ ? Bf : Af;                                     \
            int rbase_ = m_ ? col0 : row0;                                         \
            const char* g_ = (const char*)(src_ +                                  \
                (size_t)(rbase_ + lr) * DIM + (c) * BK + lsg * 8);                 \
            uint32_t sa_ = st_ + m_ * T16 + lr * RB16 + lsg * 16;                  \
            cp16(sa_, g_);                                                         \
            cp16(sa_ + 64 * RB16, g_ + (size_t)64 * DIM * 2);                      \
        }                                                                          \
    }

    float acc[4][4][4];
#pragma unroll
    for (int i = 0; i < 4; i++)
#pragma unroll
        for (int j = 0; j < 4; j++)
#pragma unroll
            for (int u = 0; u < 4; u++) acc[i][j][u] = 0.f;

    LOAD16(0, 0); cp_commit();
    LOAD16(1, 1); cp_commit();

    const int ar = lane & 15, ac = lane >> 4;
    const int br = lane & 7, bks = (lane >> 3) & 1, bjj = (lane >> 4) & 1;

    int slot = 0;
    for (int c = 0; c < NCH; c++) {
        if (c < NCH - 1) cp_wait<1>(); else cp_wait<0>();
        __syncthreads();
        if (c + 2 < NCH) {
            int ns = slot + 2; if (ns >= 3) ns -= 3;
            LOAD16(c + 2, ns);
            cp_commit();
        }

        uint32_t st = sb + slot * STG16;
#pragma unroll
        for (int ks = 0; ks < 2; ks++) {
            uint32_t a[4][4];
#pragma unroll
            for (int i = 0; i < 4; i++) {
                uint32_t ad = st + (uint32_t)((wm + i * 16 + ar) * RB16 + (ks * 2 + ac) * 16);
                ldsm4(a[i], ad);
            }
            uint32_t b[2][4];
#pragma unroll
            for (int j2 = 0; j2 < 2; j2++) {
                uint32_t bd = st + T16 +
                              (uint32_t)((wn + j2 * 16 + bjj * 8 + br) * RB16 + (ks * 2 + bks) * 16);
                ldsm4(b[j2], bd);
            }
#pragma unroll
            for (int i = 0; i < 4; i++)
#pragma unroll
                for (int j = 0; j < 4; j++)
                    mma_fp16(acc[i][j], a[i], &b[j >> 1][(j & 1) * 2]);
        }
        slot++; if (slot == 3) slot = 0;
    }

    // epilogue: route by matrix, optional rope, fp32 float2 stores
    const int mat = col0 >> 10;
    float* Cm = (mat == 0) ? C0 : ((mat == 1) ? C1 : C2);
    const bool rope = (doRope != 0) && (mat < 2);
    const int colbase = (col0 & 1023) + wn;
#pragma unroll
    for (int j = 0; j < 4; j++) {
        int colm = colbase + j * 8 + (lane & 3) * 2;
        float invf = 0.f;
        if (rope) {
            int ip = (colm & 63) >> 1;
            invf = powf(10000.0f, -(float)ip * (1.0f / 32.0f));
        }
#pragma unroll
        for (int i = 0; i < 4; i++) {
            int row = row0 + wm + i * 16 + (lane >> 2);
            float2 v0 = {acc[i][j][0], acc[i][j][1]};
            float2 v1 = {acc[i][j][2], acc[i][j][3]};
            if (rope) {
                float s, cc;
                sincosf((float)row * invf, &s, &cc);
                v0 = {v0.x * cc - v0.y * s, v0.x * s + v0.y * cc};
                sincosf((float)(row + 8) * invf, &s, &cc);
                v1 = {v1.x * cc - v1.y * s, v1.x * s + v1.y * cc};
            }
            *(float2*)(Cm + (size_t)row * DIM + colm) = v0;
            *(float2*)(Cm + (size_t)(row + 8) * DIM + colm) = v1;
        }
    }
#undef LOAD16
}

// ---------------- tiled attention (zeroing of `full` fused in) ----------------
#define KVS 68
#define SK 0
#define SV (128 * KVS)                  // 8704
#define SQ (SV + 128 * KVS)             // 17408
#define SWL (SQ + 64 * 64)              // 21504
#define SWG (SWL + 8 * 8 * 40)          // 24064
#define ATT_FLOATS (SWG + 8 * 8 * 32)   // 26112
#define ATT_SMEM (ATT_FLOATS * 4)       // 104448 bytes

__global__ __launch_bounds__(256) void attn_kernel(const float* __restrict__ Q,
                                                   const float* __restrict__ K,
                                                   const float* __restrict__ V,
                                                   __half* __restrict__ CF,
                                                   float* __restrict__ full) {
    extern __shared__ float sm[];
    const int tid = threadIdx.x;
    const int wid = tid >> 5, lane = tid & 31;
    const int t0 = blockIdx.x * 64;
    const int h = blockIdx.y;

    // load K/V rows: 0..95 = window [t0-16, t0+79], 96..127 = globals
#pragma unroll
    for (int pass = 0; pass < 8; pass++) {
        int task = tid + pass * 256;
        int r = task >> 4;
        int c4 = task & 15;
        int p = (r < 96) ? (t0 - WIN + r) : ((r - 96) * 64);
        float4 kv = {0.f, 0.f, 0.f, 0.f}, vv = {0.f, 0.f, 0.f, 0.f};
        if (p >= 0 && p < TT) {
            kv = *(const float4*)(K + (size_t)p * DIM + h * HD + c4 * 4);
            vv = *(const float4*)(V + (size_t)p * DIM + h * HD + c4 * 4);
        }
        *(float4*)&sm[SK + r * KVS + c4 * 4] = kv;
        *(float4*)&sm[SV + r * KVS + c4 * 4] = vv;
    }
    // load Q rows
#pragma unroll
    for (int pass = 0; pass < 4; pass++) {
        int task = tid + pass * 256;
        int tt = task >> 4;
        int c4 = task & 15;
        *(float4*)&sm[SQ + tt * 64 + c4 * 4] =
            *(const float4*)(Q + (size_t)(t0 + tt) * DIM + h * HD + c4 * 4);
    }
    __syncthreads();

    // phase 1: scores + softmax + scatter (+zero full rows)
    for (int it = 0; it < 8; it++) {
        const int trel = wid * 8 + it;
        const int t = t0 + trel;
        float* rowp = full + ((size_t)h * TT + t) * TT;

        float4 z4 = {0.f, 0.f, 0.f, 0.f};
#pragma unroll
        for (int z = 0; z < 16; z++) *(float4*)(rowp + (z * 32 + lane) * 4) = z4;

        int rowi[3];
        bool have[3];
        float sc[3] = {0.f, 0.f, 0.f};
#pragma unroll
        for (int u = 0; u < 3; u++) {
            int kk = u * 32 + lane;
            have[u] = (kk < NKEY);
            int r = (kk < KS) ? (trel + kk) : (96 + kk - KS);
            rowi[u] = have[u] ? r : 0;
        }
#pragma unroll
        for (int j = 0; j < 16; j++) {
            float4 q4 = *(float4*)&sm[SQ + trel * 64 + j * 4];
#pragma unroll
            for (int u = 0; u < 3; u++) {
                float4 kv = *(float4*)&sm[SK + rowi[u] * KVS + j * 4];
                sc[u] += kv.x * q4.x + kv.y * q4.y + kv.z * q4.z + kv.w * q4.w;
            }
        }
        float s0 = have[0] ? sc[0] * 0.125f : -1e30f;
        float s1 = have[1] ? sc[1] * 0.125f : -1e30f;
        float s2 = have[2] ? sc[2] * 0.125f : -1e30f;

        float m = fmaxf(fmaxf(s0, s1), s2);
#pragma unroll
        for (int o = 16; o > 0; o >>= 1) m = fmaxf(m, __shfl_xor_sync(0xFFFFFFFFu, m, o));
        float e0 = expf(s0 - m), e1 = expf(s1 - m), e2 = expf(s2 - m);
        float sum = e0 + e1 + e2;
#pragma unroll
        for (int o = 16; o > 0; o >>= 1) sum += __shfl_xor_sync(0xFFFFFFFFu, sum, o);
        const float inv = 1.f / sum;

        float* swl = &sm[SWL + wid * 320 + it * 40];
        float* swg = &sm[SWG + wid * 256 + it * 32];
        if (lane < 40) swl[lane] = 0.f;
        if (lane < 8) swl[lane + 32] = 0.f;
        swg[lane] = 0.f;
        __syncwarp();

        const int left = max(t - WIN, 0);
        const int right = min(t + WIN + 1, TT);
        float ee[3] = {e0, e1, e2};
#pragma unroll
        for (int u = 0; u < 3; u++) {
            int kk = u * 32 + lane;
            if (kk < NKEY) {
                float w = ee[u] * inv;
                if (kk < KS) {
                    swl[it + kk] = w;
                    int col = left + kk;
                    if (col < right) atomicAdd(rowp + col, w);
                } else {
                    swg[kk - KS] = w;
                    atomicAdd(rowp + (kk - KS) * 64, w);
                }
            }
        }
        __syncwarp();
    }

    // phase 2: ctx register tile (8 t's per warp, stream V rows once)
    float a0[8], a1[8];
#pragma unroll
    for (int it = 0; it < 8; it++) { a0[it] = 0.f; a1[it] = 0.f; }

    const float* swlb = &sm[SWL + wid * 320];
    const float* swgb = &sm[SWG + wid * 256];
#pragma unroll 4
    for (int j = 0; j < 40; j++) {
        int r = wid * 8 + j;
        float2 v2 = *(float2*)&sm[SV + r * KVS + 2 * lane];
#pragma unroll
        for (int it = 0; it < 8; it++) {
            float w = swlb[it * 40 + j];
            a0[it] += w * v2.x;
            a1[it] += w * v2.y;
        }
    }
#pragma unroll 4
    for (int g = 0; g < 32; g++) {
        float2 v2 = *(float2*)&sm[SV + (96 + g) * KVS + 2 * lane];
#pragma unroll
        for (int it = 0; it < 8; it++) {
            float w = swgb[it * 32 + g];
            a0[it] += w * v2.x;
            a1[it] += w * v2.y;
        }
    }

#pragma unroll
    for (int it = 0; it < 8; it++) {
        int t = t0 + wid * 8 + it;
        size_t co = ((size_t)t * DIM + h * HD) / 2 + lane;
        ((__half2*)CF)[co] = __floats2half2_rn(a0[it], a1[it]);
    }
}

// ---------------- kernel_launch ----------------
extern "C" void kernel_launch(void* const* d_in, const int* in_sizes, int n_in,
                              void* d_out, int out_size) {
    const float* x  = (const float*)d_in[0];
    const float* Wq = (const float*)d_in[1];
    const float* Wk = (const float*)d_in[2];
    const float* Wv = (const float*)d_in[3];
    const float* Wo = (const float*)d_in[4];

    float* out  = (float*)d_out;
    float* full = (float*)d_out + (size_t)TT * DIM;

    float *Q, *Kb, *V;
    cudaGetSymbolAddress((void**)&Q,  g_Q);
    cudaGetSymbolAddress((void**)&Kb, g_K);
    cudaGetSymbolAddress((void**)&V,  g_V);
    __half *xf, *wf, *cf;
    cudaGetSymbolAddress((void**)&xf, g_xf);
    cudaGetSymbolAddress((void**)&wf, g_wf);
    cudaGetSymbolAddress((void**)&cf, g_cf);

    cudaFuncSetAttribute(gemm_f16, cudaFuncAttributeMaxDynamicSharedMemorySize, GS16);
    cudaFuncSetAttribute(attn_kernel, cudaFuncAttributeMaxDynamicSharedMemorySize, ATT_SMEM);

    // conversions
    {
        int n4x = TT * DIM / 4;
        conv_f16<<<(n4x + 255) / 256, 256>>>(x, xf, n4x);
        dim3 gw(DIM * DIM / 4 / 256, 4);
        conv_w_f16<<<gw, 256>>>(Wq, Wk, Wv, Wo, wf);
    }

    // fused QKV projection + RoPE (fp16 single product)
    {
        dim3 gg(3 * DIM / 128, TT / 128);  // (24, 16)
        gemm_f16<<<gg, 256, GS16>>>(xf, wf, Q, Kb, V, 1);
    }

    // tiled attention (zeroes `full` rows, scatters, writes ctx fp16)
    {
        dim3 ga(TT / 64, NH);  // (32, 16)
        attn_kernel<<<ga, 256, ATT_SMEM>>>(Q, Kb, V, cf, full);
    }

    // output projection (fp16 single product)
    {
        dim3 gg(DIM / 128, TT / 128);  // (8, 16)
        gemm_f16<<<gg, 256, GS16>>>(cf, wf + 3 * (size_t)DIM * DIM, out, out, out, 0);
    }
}